// round 11
// baseline (speedup 1.0000x reference)
#include <cuda_runtime.h>
#include <cstdint>

// ---------------------------------------------------------------------------
// STN: conv(3x3)+relu+pool x3 -> mean -> dense x3 -> theta -> bilinear sample
// ---------------------------------------------------------------------------

typedef unsigned long long ull;

__device__ float g_pool1[16 * 127 * 127 * 16];
__device__ float g_pool2[16 * 62 * 62 * 32];
__device__ float g_mean[16 * 32];
__device__ float g_theta[16 * 6];

__device__ __forceinline__ void fma2(ull& d, ull a, ull b) {
    asm("fma.rn.f32x2 %0, %1, %2, %0;" : "+l"(d) : "l"(a), "l"(b));
}
__device__ __forceinline__ float2 asF2(ull v) {
    float2 r;
    r.x = __uint_as_float((unsigned)(v & 0xffffffffULL));
    r.y = __uint_as_float((unsigned)(v >> 32));
    return r;
}

// one ky-row of taps: 3 kx * NC channels over 2 position-rows x 4 position-cols
// operands are ulonglong2 = two fp32x2 ci-pairs (4 input channels).
template<int NC, int COB, int WSTR, int GROUPS>
__device__ __forceinline__ void do_ky(ull (&acc)[2][4][NC],
                                      const ulonglong2 (&RA)[6], const ulonglong2 (&RB)[6],
                                      const float* __restrict__ wk)
{
    #pragma unroll
    for (int kx = 0; kx < 3; ++kx) {
        #pragma unroll
        for (int cc = 0; cc < NC; ++cc) {
            ulonglong2 w2 = *(const ulonglong2*)(wk + (kx * COB + GROUPS * cc) * WSTR);
            #pragma unroll
            for (int pc = 0; pc < 4; ++pc)
                fma2(acc[0][pc][cc], RA[pc + kx].x, w2.x);
            #pragma unroll
            for (int pc = 0; pc < 4; ++pc)
                fma2(acc[1][pc][cc], RB[pc + kx].x, w2.x);
            #pragma unroll
            for (int pc = 0; pc < 4; ++pc)
                fma2(acc[0][pc][cc], RA[pc + kx].y, w2.y);
            #pragma unroll
            for (int pc = 0; pc < 4; ++pc)
                fma2(acc[1][pc][cc], RB[pc + kx].y, w2.y);
        }
    }
}

// ---------------------------------------------------------------------------
// Fused conv3x3(VALID)+bias+relu+maxpool2 (+optional mean accumulation)
// fp32x2 packed over input-channel pairs, LDS.128 loads (2 pairs per issue).
// Rolling 2-row register window (only 12 ulonglong2 of input live).
// Block: 128 thr = 4 x-slots * TILE_PY y-slots * GROUPS channel groups.
// NBI batch images per block: weights transposed once, reused.
// ---------------------------------------------------------------------------
template<int CIN, int COB, int GROUPS, int TILE_PY, int COT, int MAXB, int NBI>
__global__ __launch_bounds__(128, MAXB)
void conv_pool_kernel(const float* __restrict__ in, int inDim,
                      const float* __restrict__ w, const float* __restrict__ bias,
                      float* __restrict__ out, int outDim, int tilesX,
                      float* __restrict__ meanAcc)
{
    constexpr int THREADS = 128;
    constexpr int NC   = COB / GROUPS;
    constexpr int ISTR = CIN + 4;           // multiple of 4 -> 16B-aligned rows
    constexpr int WSTR = CIN + 4;
    constexpr int TW   = 18;                // 16 conv cols + 2
    constexpr int TH   = 2 * TILE_PY + 2;
    extern __shared__ float smem[];
    float* sIn = smem;                      // TH*TW*ISTR
    float* sW  = smem + TH * TW * ISTR;     // 9*COB*WSTR
    __shared__ float sMean[COB];

    const int tid = threadIdx.x;
    const int coBase = blockIdx.z * COB;
    const int tX = blockIdx.x % tilesX;
    const int tY = blockIdx.x / tilesX;
    const int y0 = tY * TILE_PY * 2, x0 = tX * 16;

    // ---- weights once: w[k][ci][coBase+co] -> sW[k][co][ci] ----
    constexpr int WTOT = 9 * CIN * COB;
    for (int i = tid; i < WTOT; i += THREADS) {
        int co = i % COB;
        int rest = i / COB;
        int ci = rest % CIN;
        int k  = rest / CIN;
        sW[(k * COB + co) * WSTR + ci] = w[(k * CIN + ci) * COT + coBase + co];
    }

    const int g    = tid % GROUPS;
    const int slot = tid / GROUPS;
    const int sx   = slot % 4;              // conv cols 4sx..4sx+3
    const int py   = slot / 4;              // pooled row within tile

    #pragma unroll 1
    for (int bi = 0; bi < NBI; ++bi) {
        const int b = blockIdx.y * NBI + bi;
        if (bi) __syncthreads();            // all warps done with sIn

        // ---- input window THxTWxCIN (channel-contiguous, 16B stores) ----
        constexpr int NCI4 = CIN / 4;
        for (int i = tid; i < TH * TW * NCI4; i += THREADS) {
            int ci4 = i % NCI4;
            int p   = i / NCI4;
            int ly = p / TW, lx = p - ly * TW;
            int gy = y0 + ly, gx = x0 + lx;
            float4 v = make_float4(0.f, 0.f, 0.f, 0.f);
            if (gy < inDim && gx < inDim)
                v = *(const float4*)(in + ((size_t)((b * inDim + gy) * inDim + gx)) * CIN + ci4 * 4);
            *(float4*)(sIn + p * ISTR + ci4 * 4) = v;
        }
        __syncthreads();

        ull acc[2][4][NC];
        #pragma unroll
        for (int i = 0; i < 2; i++)
            #pragma unroll
            for (int j = 0; j < 4; j++)
                #pragma unroll
                for (int k = 0; k < NC; k++) acc[i][j][k] = 0ULL;

        const float* ibase = sIn + ((2 * py) * TW + 4 * sx) * ISTR;
        const float* wbase = sW + g * WSTR;

        #pragma unroll 1
        for (int c4 = 0; c4 < CIN / 4; ++c4) {
            const float* ibc = ibase + 4 * c4;
            const float* wbc = wbase + 4 * c4;
            ulonglong2 rA[6], rB[6];
            #pragma unroll
            for (int c = 0; c < 6; ++c) rA[c] = *(const ulonglong2*)(ibc + c * ISTR);
            #pragma unroll
            for (int c = 0; c < 6; ++c) rB[c] = *(const ulonglong2*)(ibc + (TW + c) * ISTR);
            do_ky<NC, COB, WSTR, GROUPS>(acc, rA, rB, wbc);                     // ky=0: rows 0,1
            #pragma unroll
            for (int c = 0; c < 6; ++c) rA[c] = *(const ulonglong2*)(ibc + (2 * TW + c) * ISTR);
            do_ky<NC, COB, WSTR, GROUPS>(acc, rB, rA, wbc + 3 * COB * WSTR);    // ky=1: rows 1,2
            #pragma unroll
            for (int c = 0; c < 6; ++c) rB[c] = *(const ulonglong2*)(ibc + (3 * TW + c) * ISTR);
            do_ky<NC, COB, WSTR, GROUPS>(acc, rA, rB, wbc + 6 * COB * WSTR);    // ky=2: rows 2,3
        }

        // ---- horizontal add + relu(max2x2 + bias), two pooled pixels ----
        const int p = tY * TILE_PY + py;
        if (meanAcc) {
            if (tid < COB) sMean[tid] = 0.f;
            __syncthreads();
        }
        #pragma unroll
        for (int j = 0; j < 2; ++j) {
            const int q = tX * 8 + 2 * sx + j;
            const bool valid = (p < outDim) && (q < outDim);
            float res[NC];
            #pragma unroll
            for (int cc = 0; cc < NC; ++cc) {
                float2 v00 = asF2(acc[0][2 * j][cc]);
                float2 v01 = asF2(acc[0][2 * j + 1][cc]);
                float2 v10 = asF2(acc[1][2 * j][cc]);
                float2 v11 = asF2(acc[1][2 * j + 1][cc]);
                float s0 = v00.x + v00.y, s1 = v01.x + v01.y;
                float s2 = v10.x + v10.y, s3 = v11.x + v11.y;
                res[cc] = fmaxf(fmaxf(fmaxf(s0, s1), fmaxf(s2, s3)) + bias[coBase + g + GROUPS * cc], 0.f);
            }
            if (out && valid) {
                float* o = out + ((size_t)((b * outDim + p) * outDim + q)) * COT + coBase;
                #pragma unroll
                for (int cc = 0; cc < NC; ++cc) o[g + GROUPS * cc] = res[cc];
            }
            if (meanAcc && valid) {
                #pragma unroll
                for (int cc = 0; cc < NC; ++cc)
                    atomicAdd(&sMean[g + GROUPS * cc], res[cc]);
            }
        }
        if (meanAcc) {
            __syncthreads();
            if (tid < COB) atomicAdd(&meanAcc[b * COT + coBase + tid], sMean[tid]);
        }
    }
}

// ---------------------------------------------------------------------------
__global__ void zero_mean_kernel() { g_mean[threadIdx.x] = 0.f; }

__global__ void head_kernel(const float* __restrict__ D1, const float* __restrict__ db1,
                            const float* __restrict__ D2, const float* __restrict__ db2,
                            const float* __restrict__ D3, const float* __restrict__ db3)
{
    __shared__ float h0[16 * 32], h1[16 * 64], h2[16 * 32];
    int tid = threadIdx.x; // 256

    for (int i = tid; i < 512; i += 256) h0[i] = g_mean[i] * (1.0f / 900.0f);
    __syncthreads();

    for (int i = tid; i < 16 * 64; i += 256) {
        int bb = i >> 6, j = i & 63;
        float s = db1[j];
        #pragma unroll 8
        for (int c = 0; c < 32; c++) s += h0[bb * 32 + c] * D1[c * 64 + j];
        h1[i] = fmaxf(s, 0.f);
    }
    __syncthreads();

    for (int i = tid; i < 512; i += 256) {
        int bb = i >> 5, j = i & 31;
        float s = db2[j];
        #pragma unroll 8
        for (int c = 0; c < 64; c++) s += h1[bb * 64 + c] * D2[c * 32 + j];
        h2[i] = fmaxf(s, 0.f);
    }
    __syncthreads();

    if (tid < 96) {
        int bb = tid / 6, j = tid % 6;
        float s = db3[j];
        #pragma unroll 8
        for (int c = 0; c < 32; c++) s += h2[bb * 32 + c] * D3[c * 6 + j];
        g_theta[tid] = s;
    }
}

// ---------------------------------------------------------------------------
__global__ __launch_bounds__(256)
void sampler_kernel(const float* __restrict__ x, float* __restrict__ out)
{
    int t = blockIdx.x * 256 + threadIdx.x;
    int lane = t & 7;
    int pix  = t >> 3;
    int c = pix & 255;
    int r = (pix >> 8) & 255;
    int b = pix >> 16;

    const float* th = g_theta + b * 6;
    float xs = -1.f + (float)c * (2.f / 255.f);
    float ys = -1.f + (float)r * (2.f / 255.f);
    float xS = th[0] * xs + th[1] * ys + th[2];
    float yS = th[3] * xs + th[4] * ys + th[5];
    float xf = 0.5f * ((xS + 1.f) * 254.f);
    float yf = 0.5f * ((yS + 1.f) * 254.f);

    int ix0 = (int)floorf(xf), iy0 = (int)floorf(yf);
    int ix1 = ix0 + 1, iy1 = iy0 + 1;
    ix0 = min(max(ix0, 0), 255); ix1 = min(max(ix1, 0), 255);
    iy0 = min(max(iy0, 0), 255); iy1 = min(max(iy1, 0), 255);

    float X0 = (float)ix0, X1 = (float)ix1, Y0 = (float)iy0, Y1 = (float)iy1;
    float wa = (X1 - xf) * (Y1 - yf);
    float wb = (X1 - xf) * (yf - Y0);
    float wc = (xf - X0) * (Y1 - yf);
    float wd = (xf - X0) * (yf - Y0);

    const float4* pa = (const float4*)(x + ((size_t)((b * 256 + iy0) * 256 + ix0)) * 32) + lane;
    const float4* pb = (const float4*)(x + ((size_t)((b * 256 + iy1) * 256 + ix0)) * 32) + lane;
    const float4* pc = (const float4*)(x + ((size_t)((b * 256 + iy0) * 256 + ix1)) * 32) + lane;
    const float4* pd = (const float4*)(x + ((size_t)((b * 256 + iy1) * 256 + ix1)) * 32) + lane;
    float4 Ia = *pa, Ib = *pb, Ic = *pc, Id = *pd;

    float4 o;
    o.x = wa * Ia.x + wb * Ib.x + wc * Ic.x + wd * Id.x;
    o.y = wa * Ia.y + wb * Ib.y + wc * Ic.y + wd * Id.y;
    o.z = wa * Ia.z + wb * Ib.z + wc * Ic.z + wd * Id.z;
    o.w = wa * Ia.w + wb * Ib.w + wc * Ic.w + wd * Id.w;
    ((float4*)out)[t] = o;
}

// ---------------------------------------------------------------------------
extern "C" void kernel_launch(void* const* d_in, const int* in_sizes, int n_in,
                              void* d_out, int out_size)
{
    const float* x   = (const float*)d_in[0];
    const float* W1  = (const float*)d_in[1];
    const float* b1  = (const float*)d_in[2];
    const float* W2  = (const float*)d_in[3];
    const float* b2  = (const float*)d_in[4];
    const float* W3  = (const float*)d_in[5];
    const float* b3  = (const float*)d_in[6];
    const float* D1  = (const float*)d_in[7];
    const float* db1 = (const float*)d_in[8];
    const float* D2  = (const float*)d_in[9];
    const float* db2 = (const float*)d_in[10];
    const float* D3  = (const float*)d_in[11];
    const float* db3 = (const float*)d_in[12];
    float* out = (float*)d_out;

    float *p1, *p2, *mean_;
    cudaGetSymbolAddress((void**)&p1, g_pool1);
    cudaGetSymbolAddress((void**)&p2, g_pool2);
    cudaGetSymbolAddress((void**)&mean_, g_mean);

    // smem (floats): input TH*18*(CIN+4) + weights 9*COB*(CIN+4)
    const int SMEM1 = (18 * 18 * 36 + 9 * 16 * 36) * 4;   // 67392 -> 3 blk/SM
    const int SMEM2 = (10 * 18 * 20 + 9 * 32 * 20) * 4;   // 37440 -> 4 blk/SM
    const int SMEM3 = (10 * 18 * 36 + 9 * 16 * 36) * 4;   // 46656 -> 4 blk/SM
    cudaFuncSetAttribute((const void*)conv_pool_kernel<32, 16, 4, 8, 16, 3, 1>,
                         cudaFuncAttributeMaxDynamicSharedMemorySize, SMEM1);
    cudaFuncSetAttribute((const void*)conv_pool_kernel<16, 32, 8, 4, 32, 4, 2>,
                         cudaFuncAttributeMaxDynamicSharedMemorySize, SMEM2);
    cudaFuncSetAttribute((const void*)conv_pool_kernel<32, 16, 8, 4, 32, 4, 2>,
                         cudaFuncAttributeMaxDynamicSharedMemorySize, SMEM3);

    zero_mean_kernel<<<1, 512>>>();

    // stage 1: (16,256,256,32) -> (16,127,127,16); tile 8x8 pooled, NC=4
    conv_pool_kernel<32, 16, 4, 8, 16, 3, 1><<<dim3(16 * 16, 16, 1), 128, SMEM1>>>(
        x, 256, W1, b1, p1, 127, 16, nullptr);

    // stage 2: (16,127,127,16) -> (16,62,62,32); tile 8x4, 2 images/block
    conv_pool_kernel<16, 32, 8, 4, 32, 4, 2><<<dim3(8 * 16, 8, 1), 128, SMEM2>>>(
        p1, 127, W2, b2, p2, 62, 8, nullptr);

    // stage 3: (16,62,62,32) -> mean sums; tile 8x4, NC=2, 2 ch-splits,
    // 2 images/block -> grid 512 blocks = single wave at 4 blk/SM
    conv_pool_kernel<32, 16, 8, 4, 32, 4, 2><<<dim3(4 * 8, 8, 2), 128, SMEM3>>>(
        p2, 62, W3, b3, nullptr, 30, 4, mean_);

    head_kernel<<<1, 256>>>(D1, db1, D2, db2, D3, db3);

    sampler_kernel<<<32768, 256>>>(x, out);
}